// round 7
// baseline (speedup 1.0000x reference)
#include <cuda_runtime.h>
#include <cstdint>
#include <cmath>
#include <cstring>

#define N_NODES 10000
#define N_EDGES 100000
#define IN1_DIM 288
#define IN2_DIM 9
#define W_DIM   480
#define OUT_DIM 1632

// slot tables for the warp-cooperative stage 1 (built on host each launch call)
struct TPTab {
  float cgs[256][5];          // per-slot padded cg row (j entries, path_w folded)
  unsigned short dst[256];    // slot -> c-buffer element index (row*8+k); 408 = dump
};

// ---------------------------------------------------------------------------
// HOST: exact reproduction of numpy default_rng(42) CG construction.
// numpy SeedSequence -> PCG64(XSL-RR-128) -> uniforms + ziggurat normals.
// Host-only cost on the correctness/capture calls; not in timed replays.
// ---------------------------------------------------------------------------
typedef unsigned __int128 u128_t;
struct HostPcg {
  u128_t st, inc;
  void step() {
    const u128_t M = ((u128_t)2549297995355413924ULL << 64) | 4865540595714422341ULL;
    st = st * M + inc;
  }
  uint64_t n64() {
    step();  // 128-bit variant: step THEN output
    uint64_t hi = (uint64_t)(st >> 64), lo = (uint64_t)st;
    unsigned rot = (unsigned)(st >> 122);
    uint64_t x = hi ^ lo;
    return (x >> rot) | (x << ((64u - rot) & 63u));
  }
  double nd() { return (double)(n64() >> 11) * (1.0 / 9007199254740992.0); }
};

static const int tD1[15] = {1,1,1,3,3,3,3,3,3,5,5,5,5,5,5};
static const int tD2[15] = {1,3,5,1,3,3,3,5,5,1,3,3,5,5,5};
static const int tD3[15] = {1,3,5,3,1,3,5,3,5,5,3,5,1,3,5};
static const int tROWB[15] = {0,1,2,3,6,9,12,15,18,21,26,31,36,41,46};

static void build_tab(TPTab& T) {
  // --- SeedSequence(42), pool_size 4, XSHIFT 16 ---
  uint32_t pool[4];
  {
    uint32_t hc = 0x43b0d7e5u;  // INIT_A
    auto h = [&hc](uint32_t v) -> uint32_t {
      v ^= hc; hc *= 0x931e8875u; v *= hc; v ^= v >> 16; return v;  // MULT_A
    };
    // numpy mix: x*MIX_MULT_L - y*MIX_MULT_R  (SUBTRACTION, not XOR)
    auto mix = [](uint32_t x, uint32_t y) -> uint32_t {
      uint32_t r = (x * 0xca01f9ddu) - (y * 0x4973f715u);
      r ^= r >> 16;
      return r;
    };
    pool[0] = h(42u); pool[1] = h(0u); pool[2] = h(0u); pool[3] = h(0u);
    for (int s = 0; s < 4; ++s)
      for (int d = 0; d < 4; ++d)
        if (s != d) pool[d] = mix(pool[d], h(pool[s]));
  }
  uint64_t sw[4];
  {
    uint32_t hc = 0x8b51f9ddu;  // INIT_B
    uint32_t w32[8];
    for (int i = 0; i < 8; ++i) {
      uint32_t v = pool[i & 3];
      v ^= hc; hc *= 0x58f38dedu; v *= hc; v ^= v >> 16;  // MULT_B
      w32[i] = v;
    }
    for (int k = 0; k < 4; ++k)
      sw[k] = (uint64_t)w32[2 * k] | ((uint64_t)w32[2 * k + 1] << 32);
  }
  HostPcg g;
  {
    u128_t initstate = ((u128_t)sw[0] << 64) | sw[1];
    u128_t initseq   = ((u128_t)sw[2] << 64) | sw[3];
    g.st = 0; g.inc = (initseq << 1) | 1;
    g.step(); g.st += initstate; g.step();
  }

  // --- ziggurat tables: N=256, m=2^52, r per numpy ---
  double zwi[256], zfi[256]; uint64_t zki[256];
  {
    const double m = 4503599627370496.0, r = 3.6541528853610088;
    double f = exp(-0.5 * r * r);
    double v = r * f + sqrt(1.5707963267948966) * erfc(r * 0.7071067811865476);
    double q = v / f, dn = r, tn = r;
    zki[0] = (uint64_t)((dn / q) * m);  zki[1] = 0;
    zwi[0] = q / m;  zwi[255] = dn / m;
    zfi[0] = 1.0;    zfi[255] = f;
    for (int i = 254; i >= 1; --i) {
      dn = sqrt(-2.0 * log(v / dn + exp(-0.5 * dn * dn)));
      zki[i + 1] = (uint64_t)((dn / tn) * m);
      tn = dn;
      zfi[i] = exp(-0.5 * dn * dn);
      zwi[i] = dn / m;
    }
  }
  auto stdnorm = [&]() -> double {  // numpy random_standard_normal, verbatim
    const double r = 3.6541528853610088, inv_r = 0.27366123732975828;
    for (;;) {
      uint64_t rr = g.n64();
      int idx = (int)(rr & 0xff);
      rr >>= 8;
      int sign = (int)(rr & 1);
      uint64_t rabs = (rr >> 1) & 0x000fffffffffffffULL;
      double x = (double)rabs * zwi[idx];
      if (sign) x = -x;
      if (rabs < zki[idx]) return x;
      if (idx == 0) {
        double xx, yy;
        do {
          xx = -inv_r * log1p(-g.nd());
          yy = -log1p(-g.nd());
        } while (yy + yy <= xx * xx);
        return ((rabs >> 8) & 1) ? -(r + xx) : (r + xx);
      }
      if ((zfi[idx - 1] - zfi[idx]) * g.nd() + zfi[idx] < exp(-0.5 * x * x))
        return x;
    }
  };

  // --- CG draw sequence exactly as the reference (mask pass, then vals) ---
  float cgpw[15][125];
  for (int t = 0; t < 15; ++t) {
    int d1 = tD1[t], d2 = tD2[t], d3 = tD3[t], sz = d1 * d2 * d3;
    unsigned char mk[125]; int any = 0;
    for (int q = 0; q < sz; ++q) { mk[q] = (g.nd() < 0.3) ? 1 : 0; any |= mk[q]; }
    if (!any) mk[0] = 1;
    float pw = (float)(1.0 / sqrt((double)(d1 * d2)));
    for (int q = 0; q < sz; ++q) {
      float v = (float)stdnorm();               // drawn regardless of mask
      cgpw[t][q] = mk[q] ? (v * pw) : 0.0f;
    }
  }

  // --- stage-1 slots, grouped by l2 so b operands are plain registers ---
  memset(&T, 0, sizeof(T));
  for (int s = 0; s < 256; ++s) T.dst[s] = 408;  // dump row for padding
  const int gA[3] = {0, 3, 9};                 // l2=0  -> slots [0,64)
  const int gB[6] = {1, 4, 5, 6, 10, 11};      // l2=1  -> slots [64,160)
  const int gC[6] = {2, 7, 8, 12, 13, 14};     // l2=2  -> slots [160,256)
  auto fill = [&](const int* grp, int ng, int slot) {
    for (int gi = 0; gi < ng; ++gi) {
      int t = grp[gi], d1 = tD1[t], d2 = tD2[t], d3 = tD3[t];
      for (int i = 0; i < d1; ++i)
        for (int k = 0; k < d3; ++k) {
          for (int j = 0; j < d2; ++j)
            T.cgs[slot][j] = cgpw[t][(i * d2 + j) * d3 + k];
          T.dst[slot] = (unsigned short)((tROWB[t] + i) * 8 + k);
          ++slot;
        }
    }
  };
  fill(gA, 3, 0); fill(gB, 6, 64); fill(gC, 6, 160);
}

// ---------------------------------------------------------------------------
// Device scratch (no runtime allocation allowed)
// ---------------------------------------------------------------------------
__device__ int g_row_ptr[N_NODES + 1];
__device__ int g_cursor[N_NODES];
__device__ int g_edge_ids[N_EDGES];

__global__ void k_zero() {
  int i = blockIdx.x * blockDim.x + threadIdx.x;
  if (i < N_NODES) g_cursor[i] = 0;
}

__global__ void k_hist(const int* __restrict__ dst) {
  int e = blockIdx.x * blockDim.x + threadIdx.x;
  if (e < N_EDGES) atomicAdd(&g_cursor[dst[e]], 1);
}

__global__ void k_scan() {
  __shared__ int s_wsum[32];
  __shared__ int s_carry;
  const int tid = threadIdx.x, lane = tid & 31, w = tid >> 5;
  if (tid == 0) s_carry = 0;
  __syncthreads();
  for (int base = 0; base < N_NODES; base += 1024) {
    int i = base + tid;
    int v = (i < N_NODES) ? g_cursor[i] : 0;
    int x = v;
#pragma unroll
    for (int d = 1; d < 32; d <<= 1) {
      int y = __shfl_up_sync(0xffffffffu, x, d);
      if (lane >= d) x += y;
    }
    if (lane == 31) s_wsum[w] = x;
    __syncthreads();
    if (w == 0) {
      int z = s_wsum[lane];
#pragma unroll
      for (int d = 1; d < 32; d <<= 1) {
        int y = __shfl_up_sync(0xffffffffu, z, d);
        if (lane >= d) z += y;
      }
      s_wsum[lane] = z;
    }
    __syncthreads();
    int warp_excl = (w == 0) ? 0 : s_wsum[w - 1];
    int excl = s_carry + warp_excl + (x - v);
    if (i < N_NODES) { g_row_ptr[i] = excl; g_cursor[i] = 0; }
    __syncthreads();
    if (tid == 0) s_carry += s_wsum[31];
    __syncthreads();
  }
  if (tid == 0) g_row_ptr[N_NODES] = s_carry;
}

__global__ void k_scatter(const int* __restrict__ dst) {
  int e = blockIdx.x * blockDim.x + threadIdx.x;
  if (e < N_EDGES) {
    int d = dst[e];
    int pos = atomicAdd(&g_cursor[d], 1);
    g_edge_ids[g_row_ptr[d] + pos] = e;
  }
}

// ---------------------------------------------------------------------------
// Main kernel: warp per node, lane = mul u.
// Stage1 (cooperative): c[row*8+k] = sum_j b[j]*cgpw   (8 rounds, b in regs)
// Stage2 (per lane):    acc[KB+k] += w_t * sum_i a_i * c[i,k]
// ---------------------------------------------------------------------------
#define S2_1(AB, RB, KB, WI, DD) { float t0 = 0.f;                             \
  _Pragma("unroll") for (int i = 0; i < (DD); ++i)                             \
    t0 = fmaf(a[(AB) + i], cw[((RB) + i) * 8], t0);                            \
  acc[(KB)] = fmaf(wv[(WI)], t0, acc[(KB)]); }

#define S2_3(AB, RB, KB, WI, DD) { float t0 = 0.f, t1 = 0.f, t2 = 0.f;         \
  _Pragma("unroll") for (int i = 0; i < (DD); ++i) {                           \
    float4 cv = *(const float4*)&cw[((RB) + i) * 8];                           \
    float ai = a[(AB) + i];                                                    \
    t0 = fmaf(ai, cv.x, t0); t1 = fmaf(ai, cv.y, t1); t2 = fmaf(ai, cv.z, t2); } \
  acc[(KB)]     = fmaf(wv[(WI)], t0, acc[(KB)]);                               \
  acc[(KB) + 1] = fmaf(wv[(WI)], t1, acc[(KB) + 1]);                           \
  acc[(KB) + 2] = fmaf(wv[(WI)], t2, acc[(KB) + 2]); }

#define S2_5(AB, RB, KB, WI, DD) {                                             \
  float t0 = 0.f, t1 = 0.f, t2 = 0.f, t3 = 0.f, t4 = 0.f;                      \
  _Pragma("unroll") for (int i = 0; i < (DD); ++i) {                           \
    float4 cv = *(const float4*)&cw[((RB) + i) * 8];                           \
    float c4 = cw[((RB) + i) * 8 + 4];                                         \
    float ai = a[(AB) + i];                                                    \
    t0 = fmaf(ai, cv.x, t0); t1 = fmaf(ai, cv.y, t1); t2 = fmaf(ai, cv.z, t2); \
    t3 = fmaf(ai, cv.w, t3); t4 = fmaf(ai, c4, t4); }                          \
  acc[(KB)]     = fmaf(wv[(WI)], t0, acc[(KB)]);                               \
  acc[(KB) + 1] = fmaf(wv[(WI)], t1, acc[(KB) + 1]);                           \
  acc[(KB) + 2] = fmaf(wv[(WI)], t2, acc[(KB) + 2]);                           \
  acc[(KB) + 3] = fmaf(wv[(WI)], t3, acc[(KB) + 3]);                           \
  acc[(KB) + 4] = fmaf(wv[(WI)], t4, acc[(KB) + 4]); }

#define STO(OFF, DD, KB)                                                       \
  _Pragma("unroll") for (int k = 0; k < (DD); ++k)                             \
    O[(OFF) + lane * (DD) + k] = acc[(KB) + k];

__global__ void __launch_bounds__(128)
k_tp(const TPTab tab,
     const float* __restrict__ in1, const float* __restrict__ in2,
     const float* __restrict__ wt, const int* __restrict__ src,
     float* __restrict__ out)
{
  __shared__ __align__(16) float s_c[4][416];
  const int w = threadIdx.x >> 5;
  const int lane = threadIdx.x & 31;
  const int node = blockIdx.x * 4 + w;
  if (node >= N_NODES) return;
  float* cw = s_c[w];

  // hoist this lane's stage-1 cg values + destinations (loop-invariant)
  float A0c0, A1c0;
  float B0c0, B0c1, B0c2, B1c0, B1c1, B1c2, B2c0, B2c1, B2c2;
  float C0c0, C0c1, C0c2, C0c3, C0c4;
  float C1c0, C1c1, C1c2, C1c3, C1c4;
  float C2c0, C2c1, C2c2, C2c3, C2c4;
  int dA0, dA1, dB0, dB1, dB2, dC0, dC1, dC2;
  {
    int s;
    s = lane;       A0c0 = tab.cgs[s][0]; dA0 = tab.dst[s];
    s = 32 + lane;  A1c0 = tab.cgs[s][0]; dA1 = tab.dst[s];
    s = 64 + lane;  B0c0 = tab.cgs[s][0]; B0c1 = tab.cgs[s][1]; B0c2 = tab.cgs[s][2]; dB0 = tab.dst[s];
    s = 96 + lane;  B1c0 = tab.cgs[s][0]; B1c1 = tab.cgs[s][1]; B1c2 = tab.cgs[s][2]; dB1 = tab.dst[s];
    s = 128 + lane; B2c0 = tab.cgs[s][0]; B2c1 = tab.cgs[s][1]; B2c2 = tab.cgs[s][2]; dB2 = tab.dst[s];
    s = 160 + lane; C0c0 = tab.cgs[s][0]; C0c1 = tab.cgs[s][1]; C0c2 = tab.cgs[s][2]; C0c3 = tab.cgs[s][3]; C0c4 = tab.cgs[s][4]; dC0 = tab.dst[s];
    s = 192 + lane; C1c0 = tab.cgs[s][0]; C1c1 = tab.cgs[s][1]; C1c2 = tab.cgs[s][2]; C1c3 = tab.cgs[s][3]; C1c4 = tab.cgs[s][4]; dC1 = tab.dst[s];
    s = 224 + lane; C2c0 = tab.cgs[s][0]; C2c1 = tab.cgs[s][1]; C2c2 = tab.cgs[s][2]; C2c3 = tab.cgs[s][3]; C2c4 = tab.cgs[s][4]; dC2 = tab.dst[s];
  }

  float acc[51];
#pragma unroll
  for (int k = 0; k < 51; ++k) acc[k] = 0.f;

  const int beg = g_row_ptr[node];
  const int end = g_row_ptr[node + 1];

  for (int t0 = beg; t0 < end; ++t0) {
    const int e = g_edge_ids[t0];
    const int sN = src[e];

    // a: lane-local in1[src] slice; layout [32x1 | 32x3 | 32x5]
    const float* A = in1 + (size_t)sN * IN1_DIM;
    float a[9];
    a[0] = A[lane];
    { const float* p = A + 32 + lane * 3;  a[1] = p[0]; a[2] = p[1]; a[3] = p[2]; }
    { const float* p = A + 128 + lane * 5; a[4] = p[0]; a[5] = p[1]; a[6] = p[2]; a[7] = p[3]; a[8] = p[4]; }

    // b: warp-uniform
    float b[9];
    { const float* B = in2 + (size_t)e * IN2_DIM;
#pragma unroll
      for (int j = 0; j < 9; ++j) b[j] = B[j]; }

    // w: 15 coalesced 128B warp loads
    float wv[15];
    { const float* W = wt + (size_t)e * W_DIM + lane;
#pragma unroll
      for (int q = 0; q < 15; ++q) wv[q] = W[q * 32]; }

    __syncwarp();  // previous edge's stage-2 reads complete
    // stage 1: 8 rounds
    cw[dA0] = A0c0 * b[0];
    cw[dA1] = A1c0 * b[0];
    cw[dB0] = fmaf(B0c2, b[3], fmaf(B0c1, b[2], B0c0 * b[1]));
    cw[dB1] = fmaf(B1c2, b[3], fmaf(B1c1, b[2], B1c0 * b[1]));
    cw[dB2] = fmaf(B2c2, b[3], fmaf(B2c1, b[2], B2c0 * b[1]));
    cw[dC0] = fmaf(C0c4, b[8], fmaf(C0c3, b[7], fmaf(C0c2, b[6], fmaf(C0c1, b[5], C0c0 * b[4]))));
    cw[dC1] = fmaf(C1c4, b[8], fmaf(C1c3, b[7], fmaf(C1c2, b[6], fmaf(C1c1, b[5], C1c0 * b[4]))));
    cw[dC2] = fmaf(C2c4, b[8], fmaf(C2c3, b[7], fmaf(C2c2, b[6], fmaf(C2c1, b[5], C2c0 * b[4]))));
    __syncwarp();

    // stage 2: (AB, ROWB, KB, WI, d1)
    S2_1(0, 0, 0, 0, 1);
    S2_3(0, 1, 1, 1, 1);
    S2_5(0, 2, 4, 2, 1);
    S2_3(1, 3, 9, 3, 3);
    S2_1(1, 6, 12, 4, 3);
    S2_3(1, 9, 13, 5, 3);
    S2_5(1, 12, 16, 6, 3);
    S2_3(1, 15, 21, 7, 3);
    S2_5(1, 18, 24, 8, 3);
    S2_5(4, 21, 29, 9, 5);
    S2_3(4, 26, 34, 10, 5);
    S2_5(4, 31, 37, 11, 5);
    S2_1(4, 36, 42, 12, 5);
    S2_3(4, 41, 43, 13, 5);
    S2_5(4, 46, 46, 14, 5);
  }

  float* O = out + (size_t)node * OUT_DIM;
  STO(0, 1, 0);
  STO(32, 3, 1);
  STO(128, 5, 4);
  STO(288, 3, 9);
  STO(384, 1, 12);
  STO(416, 3, 13);
  STO(512, 5, 16);
  STO(672, 3, 21);
  STO(768, 5, 24);
  STO(928, 5, 29);
  STO(1088, 3, 34);
  STO(1184, 5, 37);
  STO(1344, 1, 42);
  STO(1376, 3, 43);
  STO(1472, 5, 46);
}

// ---------------------------------------------------------------------------
// Launch: CSR build + TP. Graph-capturable (kernel launches only).
// ---------------------------------------------------------------------------
extern "C" void kernel_launch(void* const* d_in, const int* in_sizes, int n_in,
                              void* d_out, int out_size) {
  const float* in1 = (const float*)d_in[0];
  const float* in2 = (const float*)d_in[1];
  const float* wt = (const float*)d_in[2];
  const int* src = (const int*)d_in[3];   // JAX default x64-disabled -> int32
  const int* dst = (const int*)d_in[4];
  float* out = (float*)d_out;

  TPTab tab;
  build_tab(tab);  // host-side; values captured into the graph as kernel params

  k_zero<<<(N_NODES + 255) / 256, 256>>>();
  k_hist<<<(N_EDGES + 255) / 256, 256>>>(dst);
  k_scan<<<1, 1024>>>();
  k_scatter<<<(N_EDGES + 255) / 256, 256>>>(dst);
  k_tp<<<(N_NODES + 3) / 4, 128>>>(tab, in1, in2, wt, src, out);
}